// round 1
// baseline (speedup 1.0000x reference)
#include <cuda_runtime.h>
#include <math.h>

#define N_NODES 8192
#define F_IN 128
#define F_OUT 64
#define NEG_SLOPE 0.2f
#define VERY_SMALL 1000000000000.0f

__device__ float g_ws[F_IN];
__device__ float g_wd[F_IN];
__device__ float g_s[N_NODES];
__device__ float g_d[N_NODES];

// Kernel 1: ws = w @ a_src, wd = w @ a_dst   (w: [128,64], a: [128,1])
__global__ void prep_kernel(const float* __restrict__ w, const float* __restrict__ a) {
    int k = threadIdx.x;  // 0..127
    float s = 0.f, d = 0.f;
    #pragma unroll
    for (int j = 0; j < F_OUT; ++j) {
        float wv = w[k * F_OUT + j];
        s += wv * a[j];
        d += wv * a[F_OUT + j];
    }
    g_ws[k] = s;
    g_wd[k] = d;
}

// Kernel 2: s[i] = h[i,:] . ws ; d[i] = h[i,:] . wd
__global__ void sd_kernel(const float* __restrict__ h) {
    __shared__ float ws[F_IN];
    __shared__ float wd[F_IN];
    int t = threadIdx.x;
    if (t < F_IN) { ws[t] = g_ws[t]; wd[t] = g_wd[t]; }
    __syncthreads();
    int i = blockIdx.x * blockDim.x + t;
    if (i >= N_NODES) return;
    const float4* hp = reinterpret_cast<const float4*>(h + (size_t)i * F_IN);
    float s = 0.f, d = 0.f;
    #pragma unroll
    for (int k = 0; k < F_IN / 4; ++k) {
        float4 v = hp[k];
        s += v.x * ws[4 * k + 0] + v.y * ws[4 * k + 1] + v.z * ws[4 * k + 2] + v.w * ws[4 * k + 3];
        d += v.x * wd[4 * k + 0] + v.y * wd[4 * k + 1] + v.z * wd[4 * k + 2] + v.w * wd[4 * k + 3];
    }
    g_s[i] = s;
    g_d[i] = d;
}

__device__ __forceinline__ float block_reduce(float v, float* red, bool is_max) {
    __syncthreads();  // protect red[] from previous use
    #pragma unroll
    for (int o = 16; o > 0; o >>= 1) {
        float other = __shfl_xor_sync(0xffffffffu, v, o);
        v = is_max ? fmaxf(v, other) : (v + other);
    }
    int warp = threadIdx.x >> 5;
    if ((threadIdx.x & 31) == 0) red[warp] = v;
    __syncthreads();
    if (warp == 0) {
        int nw = blockDim.x >> 5;
        float x = (threadIdx.x < nw) ? red[threadIdx.x] : (is_max ? -INFINITY : 0.f);
        #pragma unroll
        for (int o = 4; o > 0; o >>= 1) {
            float other = __shfl_xor_sync(0xffffffffu, x, o);
            x = is_max ? fmaxf(x, other) : (x + other);
        }
        if (threadIdx.x == 0) red[0] = x;
    }
    __syncthreads();
    return red[0];
}

// Kernel 3: one CTA per row. e = lrelu(s[i]+d[j]); mask by adj>0; softmax over j.
__global__ __launch_bounds__(256) void softmax_kernel(const float* __restrict__ adj,
                                                      float* __restrict__ out) {
    __shared__ float row[N_NODES];   // 32 KB
    __shared__ float red[8];
    const int i = blockIdx.x;
    const int t = threadIdx.x;
    const float si = g_s[i];

    const float4* ap = reinterpret_cast<const float4*>(adj + (size_t)i * N_NODES);
    const float4* dp = reinterpret_cast<const float4*>(g_d);
    float4* rp = reinterpret_cast<float4*>(row);

    // Pass 1: compute masked leaky-relu values into smem, track max
    float lmax = -INFINITY;
    #pragma unroll
    for (int c = t; c < N_NODES / 4; c += 256) {
        float4 av = ap[c];
        float4 dv = dp[c];
        float v0 = si + dv.x; v0 = v0 >= 0.f ? v0 : NEG_SLOPE * v0; v0 = (av.x > 0.f) ? v0 : -VERY_SMALL;
        float v1 = si + dv.y; v1 = v1 >= 0.f ? v1 : NEG_SLOPE * v1; v1 = (av.y > 0.f) ? v1 : -VERY_SMALL;
        float v2 = si + dv.z; v2 = v2 >= 0.f ? v2 : NEG_SLOPE * v2; v2 = (av.z > 0.f) ? v2 : -VERY_SMALL;
        float v3 = si + dv.w; v3 = v3 >= 0.f ? v3 : NEG_SLOPE * v3; v3 = (av.w > 0.f) ? v3 : -VERY_SMALL;
        rp[c] = make_float4(v0, v1, v2, v3);
        lmax = fmaxf(fmaxf(lmax, v0), fmaxf(v1, fmaxf(v2, v3)));
    }
    const float m = block_reduce(lmax, red, true);

    // Pass 2: exponentiate in smem, accumulate sum
    float lsum = 0.f;
    #pragma unroll
    for (int c = t; c < N_NODES / 4; c += 256) {
        float4 v = rp[c];
        v.x = __expf(v.x - m);
        v.y = __expf(v.y - m);
        v.z = __expf(v.z - m);
        v.w = __expf(v.w - m);
        lsum += (v.x + v.y) + (v.z + v.w);
        rp[c] = v;
    }
    const float ssum = block_reduce(lsum, red, false);
    const float inv = 1.0f / ssum;

    // Pass 3: normalize and write out
    float4* op = reinterpret_cast<float4*>(out + (size_t)i * N_NODES);
    #pragma unroll
    for (int c = t; c < N_NODES / 4; c += 256) {
        float4 v = rp[c];
        v.x *= inv; v.y *= inv; v.z *= inv; v.w *= inv;
        op[c] = v;
    }
}

extern "C" void kernel_launch(void* const* d_in, const int* in_sizes, int n_in,
                              void* d_out, int out_size) {
    const float* h   = (const float*)d_in[0];  // [8192,128]
    const float* adj = (const float*)d_in[1];  // [8192,8192]
    const float* w   = (const float*)d_in[2];  // [128,64]
    const float* a   = (const float*)d_in[3];  // [128,1]
    float* out = (float*)d_out;

    prep_kernel<<<1, F_IN>>>(w, a);
    sd_kernel<<<N_NODES / 256, 256>>>(h);
    softmax_kernel<<<N_NODES, 256>>>(adj, out);
}